// round 14
// baseline (speedup 1.0000x reference)
#include <cuda_runtime.h>

#define NPTS 6144
#define NITERS 10
#define GRID 148          // one CTA on every SM (wave-1 deterministic)
#define BLK 672           // 21 warps x 2 rows = 42-row capacity

// Scratch (static device globals — allocation-free per harness rules)
__device__ unsigned char d_M[(size_t)NPTS * NPTS];   // 37.7 MB u8 matrix
__device__ unsigned d_part[48][NPTS];                // per-column-tile rowsums
__device__ float d_v0[NPTS];
__device__ float d_v1[NPTS];
__device__ unsigned g_cnt;   // monotone grid-barrier ticket (survives replays)

__device__ __forceinline__ float fsqrt_approx(float x) {
    float r;
    asm("sqrt.approx.f32 %0, %1;" : "=f"(r) : "f"(x));
    return r;
}

// ---- packed f32x2 helpers (sm_103a) ----
typedef unsigned long long u64t;
__device__ __forceinline__ u64t pk2(float lo, float hi) {
    u64t r; asm("mov.b64 %0, {%1, %2};" : "=l"(r) : "f"(lo), "f"(hi)); return r;
}
__device__ __forceinline__ void upk2(float& lo, float& hi, u64t v) {
    asm("mov.b64 {%0, %1}, %2;" : "=f"(lo), "=f"(hi) : "l"(v));
}
__device__ __forceinline__ u64t add2(u64t a, u64t b) {
    u64t r; asm("add.rn.f32x2 %0, %1, %2;" : "=l"(r) : "l"(a), "l"(b)); return r;
}
__device__ __forceinline__ u64t mul2(u64t a, u64t b) {
    u64t r; asm("mul.rn.f32x2 %0, %1, %2;" : "=l"(r) : "l"(a), "l"(b)); return r;
}
__device__ __forceinline__ u64t fma2(u64t a, u64t b, u64t c) {
    u64t r; asm("fma.rn.f32x2 %0, %1, %2, %3;" : "=l"(r) : "l"(a), "l"(b), "l"(c));
    return r;
}

// Build M in u8 fixed-point, SYMMETRIC (R11 version — fastest measured).
// Only tiles with tj >= ti computed; mirror tile stored via in-register
// 8x8 byte transpose with direct stores. M[i][j] == M[j][i] bit-exactly.
// Rowsums for iteration 0 (x = ones) go to d_part[48][NPTS]; every slot
// written exactly once — no atomics, no zeroing.
__global__ void __launch_bounds__(256) k_build(const float* __restrict__ p2,
                                               const float* __restrict__ p3) {
    const int ti = blockIdx.y;        // row tile
    const int tj = blockIdx.x;        // col tile
    if (ti > tj) return;              // symmetric: upper triangle only

    const int tid = threadIdx.x;
    const int tx = tid & 15;          // col group within tile
    const int ty = tid >> 4;          // row group within tile
    const int C0 = tj * 128;
    const int R0 = ti * 128;
    const int j0 = C0 + tx * 8;       // 8 cols
    const int rr0 = R0 + ty * 8;      // 8 rows

    const float4* p2v = reinterpret_cast<const float4*>(p2);
    const float4* p3v = reinterpret_cast<const float4*>(p3);

    u64t ncx[4], ncy[4], n3x[4], n3y[4], n3z[4];
#pragma unroll
    for (int k = 0; k < 4; k++) {
        float4 a = __ldg(&p2v[j0 / 2 + k]);
        ncx[k] = pk2(-a.x, -a.z);
        ncy[k] = pk2(-a.y, -a.w);
    }
    {
        float q3[24];
#pragma unroll
        for (int k = 0; k < 6; k++) {
            float4 a = __ldg(&p3v[(3 * j0) / 4 + k]);
            q3[4*k] = a.x; q3[4*k+1] = a.y; q3[4*k+2] = a.z; q3[4*k+3] = a.w;
        }
#pragma unroll
        for (int k = 0; k < 4; k++) {
            n3x[k] = pk2(-q3[6*k],   -q3[6*k+3]);
            n3y[k] = pk2(-q3[6*k+1], -q3[6*k+4]);
            n3z[k] = pk2(-q3[6*k+2], -q3[6*k+5]);
        }
    }
    float rx[8], ry[8];
#pragma unroll
    for (int k = 0; k < 4; k++) {
        float4 a = __ldg(&p2v[rr0 / 2 + k]);
        rx[2*k] = a.x; ry[2*k] = a.y; rx[2*k+1] = a.z; ry[2*k+1] = a.w;
    }
    float r3[24];
#pragma unroll
    for (int k = 0; k < 6; k++) {
        float4 a = __ldg(&p3v[(3 * rr0) / 4 + k]);
        r3[4*k] = a.x; r3[4*k+1] = a.y; r3[4*k+2] = a.z; r3[4*k+3] = a.w;
    }

    const u64t NEG2  = pk2(-2.0f, -2.0f);
    const u64t NEGK  = pk2(-25500.0f, -25500.0f);
    const u64t MAGIC = pk2(8388863.0f, 8388863.0f);

    unsigned tl[8], th[8], rs[8];
#pragma unroll
    for (int r = 0; r < 8; r++) {
        const u64t sx2 = pk2(rx[r], rx[r]);
        const u64t sy2 = pk2(ry[r], ry[r]);
        const u64t sx3 = pk2(r3[3*r],   r3[3*r]);
        const u64t sy3 = pk2(r3[3*r+1], r3[3*r+1]);
        const u64t sz3 = pk2(r3[3*r+2], r3[3*r+2]);
        unsigned u[8];
#pragma unroll
        for (int p = 0; p < 4; p++) {
            u64t dx = add2(sx2, ncx[p]);
            u64t dy = add2(sy2, ncy[p]);
            u64t a  = fma2(dx, dx, mul2(dy, dy));
            u64t d0 = add2(sx3, n3x[p]);
            u64t d1 = add2(sy3, n3y[p]);
            u64t d2 = add2(sz3, n3z[p]);
            u64t b  = fma2(d2, d2, fma2(d1, d1, mul2(d0, d0)));
            u64t ab = mul2(a, b);
            u64t apb = add2(a, b);
            float ab0, ab1;
            upk2(ab0, ab1, ab);
            u64t s  = pk2(fsqrt_approx(ab0), fsqrt_approx(ab1));
            u64t cr = fma2(NEG2, s, apb);       // (sqrt a - sqrt b)^2
            u64t t  = fma2(NEGK, cr, MAGIC);    // 2^23 + 255 - 25500*cr
            float t0, t1;
            upk2(t0, t1, t);
            t0 = fminf(fmaxf(t0, 8388608.0f), 8388863.0f);
            t1 = fminf(fmaxf(t1, 8388608.0f), 8388863.0f);
            u[2*p]   = __float_as_uint(t0);     // byte = low 8 mantissa bits
            u[2*p+1] = __float_as_uint(t1);
        }
        unsigned w0 = __byte_perm(__byte_perm(u[0], u[1], 0x0040),
                                  __byte_perm(u[2], u[3], 0x0040), 0x5410);
        unsigned w1 = __byte_perm(__byte_perm(u[4], u[5], 0x0040),
                                  __byte_perm(u[6], u[7], 0x0040), 0x5410);
        *reinterpret_cast<uint2*>(&d_M[(size_t)(rr0 + r) * NPTS + j0]) =
            make_uint2(w0, w1);
        tl[r] = w0; th[r] = w1;
        rs[r] = __dp4a(w0, 0x01010101u, __dp4a(w1, 0x01010101u, 0u));
    }

    // Row partials: reduce rs[] across tx (16 lanes of a half-warp).
#pragma unroll
    for (int r = 0; r < 8; r++) {
        unsigned v = rs[r];
        v += __shfl_xor_sync(0xffffffffu, v, 1);
        v += __shfl_xor_sync(0xffffffffu, v, 2);
        v += __shfl_xor_sync(0xffffffffu, v, 4);
        v += __shfl_xor_sync(0xffffffffu, v, 8);
        if (tx == 0) d_part[tj][rr0 + r] = v;
    }

    __shared__ unsigned scol[128][17];   // padded col-partial staging

    if (ti != tj) {
        // 8x8 byte transpose in registers (PRMT).
        unsigned ol[8], oh[8];
#pragma unroll
        for (int half = 0; half < 2; half++) {          // out cols 0-3 / 4-7
            const unsigned* in = half ? th : tl;
            unsigned* o03 = half ? (ol + 4) : ol;
            unsigned* o47 = half ? (oh + 4) : oh;
            unsigned p0 = __byte_perm(in[0], in[1], 0x5140);
            unsigned p1 = __byte_perm(in[0], in[1], 0x7362);
            unsigned q0 = __byte_perm(in[2], in[3], 0x5140);
            unsigned q1 = __byte_perm(in[2], in[3], 0x7362);
            o03[0] = __byte_perm(p0, q0, 0x5410);
            o03[1] = __byte_perm(p0, q0, 0x7632);
            o03[2] = __byte_perm(p1, q1, 0x5410);
            o03[3] = __byte_perm(p1, q1, 0x7632);
            unsigned s0 = __byte_perm(in[4], in[5], 0x5140);
            unsigned s1 = __byte_perm(in[4], in[5], 0x7362);
            unsigned t0 = __byte_perm(in[6], in[7], 0x5140);
            unsigned t1 = __byte_perm(in[6], in[7], 0x7362);
            o47[0] = __byte_perm(s0, t0, 0x5410);
            o47[1] = __byte_perm(s0, t0, 0x7632);
            o47[2] = __byte_perm(s1, t1, 0x5410);
            o47[3] = __byte_perm(s1, t1, 0x7632);
        }
        // Store mirror tile + per-thread column sums.
#pragma unroll
        for (int c = 0; c < 8; c++) {
            *reinterpret_cast<uint2*>(
                &d_M[(size_t)(j0 + c) * NPTS + rr0]) = make_uint2(ol[c], oh[c]);
            scol[tx * 8 + c][ty] =
                __dp4a(ol[c], 0x01010101u, __dp4a(oh[c], 0x01010101u, 0u));
        }
        __syncthreads();
        if (tid < 128) {
            unsigned s = 0;
#pragma unroll
            for (int t = 0; t < 16; t++) s += scol[tid][t];
            d_part[ti][C0 + tid] = s;   // col partials = mirror-tile rows
        }
    }
}

// Software grid barrier. Monotone ticket counter: works across graph replays
// without reset (counter is always a multiple of GRID at barrier boundaries).
__device__ __forceinline__ void grid_barrier() {
    __syncthreads();
    if (threadIdx.x == 0) {
        __threadfence();
        unsigned old = atomicAdd(&g_cnt, 1u);
        unsigned target = old - (old % GRID) + GRID;
        while (*((volatile unsigned*)&g_cnt) < target) __nanosleep(32);
    }
    __syncthreads();
}

// Persistent kernel on ALL 148 SMs: iterations 1..9 + final normalization.
// Uneven static row partition: CTAs 0..75 own 42 rows, 76..147 own 41
// (total exactly 6144). 21 warps x 2 rows; warp 20 predicates its second
// row when the CTA owns 41. One CTA per SM keeps its M rows hot in L1
// (__ldg); x/y vectors bypass stale L1 (__ldcg). x quantized to a single
// u8 plane scaled by its max; exact u32 dp4a accumulation; norm from
// unquantized floats (reference semantics).
// SYNC RULE (R13 hang root cause): every __shfl_xor_sync with a full mask
// must be executed by FULL warps. The prologue therefore runs on exactly
// 384 threads (12 full warps) with clamped reads, not 8*cnt threads.
__global__ void __launch_bounds__(BLK) k_iter(float* __restrict__ out) {
    __shared__ unsigned sxq[NPTS / 4];    // u8 plane of xq
    __shared__ float red[21];
    __shared__ float redm[21];

    const int tid = threadIdx.x;
    const int warp = tid >> 5, lane = tid & 31;
    const int b = blockIdx.x;
    const int cnt = 41 + (b < 76 ? 1 : 0);
    const int start = 41 * b + (b < 76 ? b : 76);
    const int r0 = start + warp * 2;
    const bool has2 = (warp * 2 + 1) < cnt;
    const int r1 = has2 ? (r0 + 1) : r0;          // clamp (load dup, no store)
    const uint4* M4  = reinterpret_cast<const uint4*>(d_M);
    const uint4* sq4 = reinterpret_cast<const uint4*>(sxq);
    const size_t rb0 = (size_t)r0 * (NPTS / 16);
    const size_t rb1 = (size_t)r1 * (NPTS / 16);

    // Prologue: v1[row] = (sum of 48 column-tile partials)/255 for this
    // CTA's rows. 12 FULL warps participate (tid < 384); row index clamped
    // so padded lanes do harmless reads; store guarded. Exact (sums < 2^24).
    if (tid < 384) {
        const int rloc = tid >> 3;                    // 0..47 (padded)
        const int seg  = tid & 7;
        const int row  = min(start + rloc, NPTS - 1);
        unsigned s = 0;
#pragma unroll
        for (int a = 0; a < 6; a++)
            s += d_part[seg * 6 + a][row];
        s += __shfl_xor_sync(0xffffffffu, s, 1);
        s += __shfl_xor_sync(0xffffffffu, s, 2);
        s += __shfl_xor_sync(0xffffffffu, s, 4);
        if (seg == 0 && rloc < cnt)
            d_v1[row] = (float)s * (1.0f / 255.0f);
    }
    grid_barrier();

    for (int k = 1; k < NITERS; k++) {
        float* __restrict__ y = (k & 1) ? d_v0 : d_v1;
        const float4* xv = reinterpret_cast<const float4*>(
            (k & 1) ? d_v1 : d_v0);

        // Stage x (L2 only — L1 may hold stale lines), norm + max.
        // Bounds-guarded loads; shuffles AFTER the loop run on all threads.
        float4 v[3];
        float ss = 0.0f, mx = 0.0f;
#pragma unroll
        for (int t = 0; t < 3; t++) {
            const int f = tid + BLK * t;
            if (f < NPTS / 4) {
                v[t] = __ldcg(&xv[f]);
                ss = fmaf(v[t].x, v[t].x, fmaf(v[t].y, v[t].y,
                     fmaf(v[t].z, v[t].z, fmaf(v[t].w, v[t].w, ss))));
                mx = fmaxf(mx, fmaxf(fmaxf(v[t].x, v[t].y),
                                     fmaxf(v[t].z, v[t].w)));
            }
        }
#pragma unroll
        for (int o = 16; o; o >>= 1) {
            ss += __shfl_xor_sync(0xffffffffu, ss, o);
            mx = fmaxf(mx, __shfl_xor_sync(0xffffffffu, mx, o));
        }
        if (lane == 0) { red[warp] = ss; redm[warp] = mx; }
        __syncthreads();
        ss = 0.0f; mx = 0.0f;
#pragma unroll
        for (int w = 0; w < 21; w++) {
            ss += red[w];
            mx = fmaxf(mx, redm[w]);
        }

        const float inv = 1.0f / (sqrtf(ss) + 1e-6f);
        const float qs  = 255.0f / mx;                 // max-scaled u8 quant
        const float outsc = mx * inv * (1.0f / 65025.0f);

#pragma unroll
        for (int t = 0; t < 3; t++) {
            const int f = tid + BLK * t;
            if (f < NPTS / 4) {
                unsigned q0 = __float2uint_rn(v[t].x * qs);
                unsigned q1 = __float2uint_rn(v[t].y * qs);
                unsigned q2 = __float2uint_rn(v[t].z * qs);
                unsigned q3 = __float2uint_rn(v[t].w * qs);
                sxq[f] = q0 | (q1 << 8) | (q2 << 16) | (q3 << 24);
            }
        }
        __syncthreads();

        unsigned a0 = 0, a1 = 0;
#pragma unroll
        for (int it = 0; it < 12; it++) {
            const int c = it * 32 + lane;     // 16-column chunk id
            uint4 xq = sq4[c];
            uint4 m0 = __ldg(&M4[rb0 + c]);                // L1-cached
            uint4 m1 = __ldg(&M4[rb1 + c]);
            a0 = __dp4a(m0.x, xq.x, a0);
            a0 = __dp4a(m0.y, xq.y, a0);
            a0 = __dp4a(m0.z, xq.z, a0);
            a0 = __dp4a(m0.w, xq.w, a0);
            a1 = __dp4a(m1.x, xq.x, a1);
            a1 = __dp4a(m1.y, xq.y, a1);
            a1 = __dp4a(m1.z, xq.z, a1);
            a1 = __dp4a(m1.w, xq.w, a1);
        }
#pragma unroll
        for (int o = 16; o; o >>= 1) {
            a0 += __shfl_xor_sync(0xffffffffu, a0, o);
            a1 += __shfl_xor_sync(0xffffffffu, a1, o);
        }
        if (lane == 0) {
            y[r0] = (float)a0 * outsc;
            if (has2) y[r0 + 1] = (float)a1 * outsc;
        }
        grid_barrier();   // includes __threadfence before arrival
    }

    // Final normalization. Last result is in d_v0 (k=9 wrote y=d_v0).
    {
        float ss = 0.0f;
        const float4* xv = reinterpret_cast<const float4*>(d_v0);
#pragma unroll
        for (int t = 0; t < 3; t++) {
            const int f = tid + BLK * t;
            if (f < NPTS / 4) {
                float4 v = __ldcg(&xv[f]);
                ss = fmaf(v.x, v.x, fmaf(v.y, v.y,
                     fmaf(v.z, v.z, fmaf(v.w, v.w, ss))));
            }
        }
#pragma unroll
        for (int o = 16; o; o >>= 1) ss += __shfl_xor_sync(0xffffffffu, ss, o);
        if (lane == 0) red[warp] = ss;
        __syncthreads();
        ss = 0.0f;
#pragma unroll
        for (int w = 0; w < 21; w++) ss += red[w];
        const float inv = 1.0f / (sqrtf(ss) + 1e-6f);
        if (tid < cnt) {
            const int i = start + tid;
            out[i] = __ldcg(&d_v0[i]) * inv;   // no sync below this point
        }
    }
}

extern "C" void kernel_launch(void* const* d_in, const int* in_sizes, int n_in,
                              void* d_out, int out_size) {
    const float* p2 = (const float*)d_in[0];  // ipts2d (N,2) fp32
    const float* p3 = (const float*)d_in[1];  // ipts3d (N,3) fp32

    dim3 bgrid(48, 48);                       // 128x128 tiles; ti<=tj compute
    k_build<<<bgrid, 256>>>(p2, p3);
    k_iter<<<GRID, BLK>>>((float*)d_out);     // persistent: iters 1-9 + final
}

// round 15
// speedup vs baseline: 1.0416x; 1.0416x over previous
#include <cuda_runtime.h>

#define NPTS 6144
#define NITERS 10
#define GRID 128          // persistent grid: 1 CTA/SM (best measured shape)
#define BLK 768           // 24 warps x 2 rows = 48 rows/CTA

// Scratch (static device globals — allocation-free per harness rules)
__device__ unsigned char d_M[(size_t)NPTS * NPTS];   // 37.7 MB u8 matrix
__device__ unsigned d_part[48][NPTS];                // per-column-tile rowsums
__device__ float d_v0[NPTS];
__device__ float d_v1[NPTS];
__device__ float2 d_pn[GRID];   // per-CTA {sum y^2, max y} partials
__device__ unsigned g_cnt;   // monotone grid-barrier ticket (survives replays)

__device__ __forceinline__ float fsqrt_approx(float x) {
    float r;
    asm("sqrt.approx.f32 %0, %1;" : "=f"(r) : "f"(x));
    return r;
}

// ---- packed f32x2 helpers (sm_103a) ----
typedef unsigned long long u64t;
__device__ __forceinline__ u64t pk2(float lo, float hi) {
    u64t r; asm("mov.b64 %0, {%1, %2};" : "=l"(r) : "f"(lo), "f"(hi)); return r;
}
__device__ __forceinline__ void upk2(float& lo, float& hi, u64t v) {
    asm("mov.b64 {%0, %1}, %2;" : "=f"(lo), "=f"(hi) : "l"(v));
}
__device__ __forceinline__ u64t add2(u64t a, u64t b) {
    u64t r; asm("add.rn.f32x2 %0, %1, %2;" : "=l"(r) : "l"(a), "l"(b)); return r;
}
__device__ __forceinline__ u64t mul2(u64t a, u64t b) {
    u64t r; asm("mul.rn.f32x2 %0, %1, %2;" : "=l"(r) : "l"(a), "l"(b)); return r;
}
__device__ __forceinline__ u64t fma2(u64t a, u64t b, u64t c) {
    u64t r; asm("fma.rn.f32x2 %0, %1, %2, %3;" : "=l"(r) : "l"(a), "l"(b), "l"(c));
    return r;
}

// Build M in u8 fixed-point, SYMMETRIC (R11 version — fastest measured).
// Only tiles with tj >= ti computed; mirror tile stored via in-register
// 8x8 byte transpose with direct stores. M[i][j] == M[j][i] bit-exactly.
// Rowsums for iteration 0 (x = ones) go to d_part[48][NPTS]; every slot
// written exactly once — no atomics, no zeroing.
__global__ void __launch_bounds__(256) k_build(const float* __restrict__ p2,
                                               const float* __restrict__ p3) {
    const int ti = blockIdx.y;        // row tile
    const int tj = blockIdx.x;        // col tile
    if (ti > tj) return;              // symmetric: upper triangle only

    const int tid = threadIdx.x;
    const int tx = tid & 15;          // col group within tile
    const int ty = tid >> 4;          // row group within tile
    const int C0 = tj * 128;
    const int R0 = ti * 128;
    const int j0 = C0 + tx * 8;       // 8 cols
    const int rr0 = R0 + ty * 8;      // 8 rows

    const float4* p2v = reinterpret_cast<const float4*>(p2);
    const float4* p3v = reinterpret_cast<const float4*>(p3);

    u64t ncx[4], ncy[4], n3x[4], n3y[4], n3z[4];
#pragma unroll
    for (int k = 0; k < 4; k++) {
        float4 a = __ldg(&p2v[j0 / 2 + k]);
        ncx[k] = pk2(-a.x, -a.z);
        ncy[k] = pk2(-a.y, -a.w);
    }
    {
        float q3[24];
#pragma unroll
        for (int k = 0; k < 6; k++) {
            float4 a = __ldg(&p3v[(3 * j0) / 4 + k]);
            q3[4*k] = a.x; q3[4*k+1] = a.y; q3[4*k+2] = a.z; q3[4*k+3] = a.w;
        }
#pragma unroll
        for (int k = 0; k < 4; k++) {
            n3x[k] = pk2(-q3[6*k],   -q3[6*k+3]);
            n3y[k] = pk2(-q3[6*k+1], -q3[6*k+4]);
            n3z[k] = pk2(-q3[6*k+2], -q3[6*k+5]);
        }
    }
    float rx[8], ry[8];
#pragma unroll
    for (int k = 0; k < 4; k++) {
        float4 a = __ldg(&p2v[rr0 / 2 + k]);
        rx[2*k] = a.x; ry[2*k] = a.y; rx[2*k+1] = a.z; ry[2*k+1] = a.w;
    }
    float r3[24];
#pragma unroll
    for (int k = 0; k < 6; k++) {
        float4 a = __ldg(&p3v[(3 * rr0) / 4 + k]);
        r3[4*k] = a.x; r3[4*k+1] = a.y; r3[4*k+2] = a.z; r3[4*k+3] = a.w;
    }

    const u64t NEG2  = pk2(-2.0f, -2.0f);
    const u64t NEGK  = pk2(-25500.0f, -25500.0f);
    const u64t MAGIC = pk2(8388863.0f, 8388863.0f);

    unsigned tl[8], th[8], rs[8];
#pragma unroll
    for (int r = 0; r < 8; r++) {
        const u64t sx2 = pk2(rx[r], rx[r]);
        const u64t sy2 = pk2(ry[r], ry[r]);
        const u64t sx3 = pk2(r3[3*r],   r3[3*r]);
        const u64t sy3 = pk2(r3[3*r+1], r3[3*r+1]);
        const u64t sz3 = pk2(r3[3*r+2], r3[3*r+2]);
        unsigned u[8];
#pragma unroll
        for (int p = 0; p < 4; p++) {
            u64t dx = add2(sx2, ncx[p]);
            u64t dy = add2(sy2, ncy[p]);
            u64t a  = fma2(dx, dx, mul2(dy, dy));
            u64t d0 = add2(sx3, n3x[p]);
            u64t d1 = add2(sy3, n3y[p]);
            u64t d2 = add2(sz3, n3z[p]);
            u64t b  = fma2(d2, d2, fma2(d1, d1, mul2(d0, d0)));
            u64t ab = mul2(a, b);
            u64t apb = add2(a, b);
            float ab0, ab1;
            upk2(ab0, ab1, ab);
            u64t s  = pk2(fsqrt_approx(ab0), fsqrt_approx(ab1));
            u64t cr = fma2(NEG2, s, apb);       // (sqrt a - sqrt b)^2
            u64t t  = fma2(NEGK, cr, MAGIC);    // 2^23 + 255 - 25500*cr
            float t0, t1;
            upk2(t0, t1, t);
            t0 = fminf(fmaxf(t0, 8388608.0f), 8388863.0f);
            t1 = fminf(fmaxf(t1, 8388608.0f), 8388863.0f);
            u[2*p]   = __float_as_uint(t0);     // byte = low 8 mantissa bits
            u[2*p+1] = __float_as_uint(t1);
        }
        unsigned w0 = __byte_perm(__byte_perm(u[0], u[1], 0x0040),
                                  __byte_perm(u[2], u[3], 0x0040), 0x5410);
        unsigned w1 = __byte_perm(__byte_perm(u[4], u[5], 0x0040),
                                  __byte_perm(u[6], u[7], 0x0040), 0x5410);
        *reinterpret_cast<uint2*>(&d_M[(size_t)(rr0 + r) * NPTS + j0]) =
            make_uint2(w0, w1);
        tl[r] = w0; th[r] = w1;
        rs[r] = __dp4a(w0, 0x01010101u, __dp4a(w1, 0x01010101u, 0u));
    }

    // Row partials: reduce rs[] across tx (16 lanes of a half-warp).
#pragma unroll
    for (int r = 0; r < 8; r++) {
        unsigned v = rs[r];
        v += __shfl_xor_sync(0xffffffffu, v, 1);
        v += __shfl_xor_sync(0xffffffffu, v, 2);
        v += __shfl_xor_sync(0xffffffffu, v, 4);
        v += __shfl_xor_sync(0xffffffffu, v, 8);
        if (tx == 0) d_part[tj][rr0 + r] = v;
    }

    __shared__ unsigned scol[128][17];   // padded col-partial staging

    if (ti != tj) {
        // 8x8 byte transpose in registers (PRMT).
        unsigned ol[8], oh[8];
#pragma unroll
        for (int half = 0; half < 2; half++) {          // out cols 0-3 / 4-7
            const unsigned* in = half ? th : tl;
            unsigned* o03 = half ? (ol + 4) : ol;
            unsigned* o47 = half ? (oh + 4) : oh;
            unsigned p0 = __byte_perm(in[0], in[1], 0x5140);
            unsigned p1 = __byte_perm(in[0], in[1], 0x7362);
            unsigned q0 = __byte_perm(in[2], in[3], 0x5140);
            unsigned q1 = __byte_perm(in[2], in[3], 0x7362);
            o03[0] = __byte_perm(p0, q0, 0x5410);
            o03[1] = __byte_perm(p0, q0, 0x7632);
            o03[2] = __byte_perm(p1, q1, 0x5410);
            o03[3] = __byte_perm(p1, q1, 0x7632);
            unsigned s0 = __byte_perm(in[4], in[5], 0x5140);
            unsigned s1 = __byte_perm(in[4], in[5], 0x7362);
            unsigned t0 = __byte_perm(in[6], in[7], 0x5140);
            unsigned t1 = __byte_perm(in[6], in[7], 0x7362);
            o47[0] = __byte_perm(s0, t0, 0x5410);
            o47[1] = __byte_perm(s0, t0, 0x7632);
            o47[2] = __byte_perm(s1, t1, 0x5410);
            o47[3] = __byte_perm(s1, t1, 0x7632);
        }
        // Store mirror tile + per-thread column sums.
#pragma unroll
        for (int c = 0; c < 8; c++) {
            *reinterpret_cast<uint2*>(
                &d_M[(size_t)(j0 + c) * NPTS + rr0]) = make_uint2(ol[c], oh[c]);
            scol[tx * 8 + c][ty] =
                __dp4a(ol[c], 0x01010101u, __dp4a(oh[c], 0x01010101u, 0u));
        }
        __syncthreads();
        if (tid < 128) {
            unsigned s = 0;
#pragma unroll
            for (int t = 0; t < 16; t++) s += scol[tid][t];
            d_part[ti][C0 + tid] = s;   // col partials = mirror-tile rows
        }
    }
}

// Software grid barrier. Monotone ticket counter: works across graph replays
// without reset (counter is always a multiple of GRID at barrier boundaries).
__device__ __forceinline__ void grid_barrier() {
    __syncthreads();
    if (threadIdx.x == 0) {
        __threadfence();
        unsigned old = atomicAdd(&g_cnt, 1u);
        unsigned target = old - (old % GRID) + GRID;
        while (*((volatile unsigned*)&g_cnt) < target) __nanosleep(32);
    }
    __syncthreads();
}

// Persistent kernel (R11 shape): iterations 1..9 + final normalization.
// NEW vs R11: the {||y||^2, max y} reduction is PRODUCER-SIDE. Each CTA
// publishes a per-CTA partial (d_pn[b]) computed from the y values already
// in registers; the next iteration's consumers reduce 128 partials (1KB)
// instead of re-reducing the whole 6144-vector. qs = 255/mx and the
// quantized xq stream depend only on ratios of y values, which are
// unchanged — the integer dp4a math is bit-identical to R11.
// M rows hot in L1 (__ldg); x and d_pn bypass stale L1 (__ldcg).
__global__ void __launch_bounds__(BLK) k_iter(float* __restrict__ out) {
    __shared__ unsigned sxq[NPTS / 4];    // u8 plane of xq
    __shared__ float swp[24];             // warp partials: sum y^2
    __shared__ float swm[24];             // warp partials: max y
    __shared__ float sred[2];             // broadcast {ss, mx}
    __shared__ float sv48[48];            // k==1 row values

    const int tid = threadIdx.x;
    const int warp = tid >> 5, lane = tid & 31;
    const int r0 = blockIdx.x * 48 + warp * 2;
    const uint4* M4  = reinterpret_cast<const uint4*>(d_M);
    const uint4* sq4 = reinterpret_cast<const uint4*>(sxq);
    const size_t rb = (size_t)r0 * (NPTS / 16);

    // Prologue: v1[row] = (sum of 48 column-tile partials)/255 for this
    // CTA's 48 rows (12 FULL warps; exact u32). Also publish d_pn[b].
    if (tid < 384) {
        const int rloc = tid >> 3;
        const int seg  = tid & 7;
        const int row  = blockIdx.x * 48 + rloc;
        unsigned s = 0;
#pragma unroll
        for (int a = 0; a < 6; a++)
            s += d_part[seg * 6 + a][row];
        s += __shfl_xor_sync(0xffffffffu, s, 1);
        s += __shfl_xor_sync(0xffffffffu, s, 2);
        s += __shfl_xor_sync(0xffffffffu, s, 4);
        if (seg == 0) {
            const float v = (float)s * (1.0f / 255.0f);
            d_v1[row] = v;
            sv48[rloc] = v;
        }
    }
    __syncthreads();
    if (tid == 0) {
        float ps = 0.0f, pm = 0.0f;
#pragma unroll
        for (int i = 0; i < 48; i++) {
            const float v = sv48[i];
            ps = fmaf(v, v, ps);
            pm = fmaxf(pm, v);
        }
        d_pn[blockIdx.x] = make_float2(ps, pm);
    }
    grid_barrier();

    for (int k = 1; k < NITERS; k++) {
        float* __restrict__ y = (k & 1) ? d_v0 : d_v1;
        const float4* xv = reinterpret_cast<const float4*>(
            (k & 1) ? d_v1 : d_v0);

        // Global {ss, mx} from 128 per-CTA partials (warp 0 only).
        if (warp == 0) {
            float ssl = 0.0f, mxl = 0.0f;
#pragma unroll
            for (int t = 0; t < 4; t++) {
                const float2 p = __ldcg(&d_pn[lane + 32 * t]);
                ssl += p.x;
                mxl = fmaxf(mxl, p.y);
            }
#pragma unroll
            for (int o = 16; o; o >>= 1) {
                ssl += __shfl_xor_sync(0xffffffffu, ssl, o);
                mxl = fmaxf(mxl, __shfl_xor_sync(0xffffffffu, mxl, o));
            }
            if (lane == 0) { sred[0] = ssl; sred[1] = mxl; }
        }
        __syncthreads();
        const float ss = sred[0];
        const float mx = sred[1];

        const float inv = 1.0f / (sqrtf(ss) + 1e-6f);
        const float qs  = 255.0f / mx;                 // max-scaled u8 quant
        const float outsc = mx * inv * (1.0f / 65025.0f);

        // Stage + quantize x in one pass (L2 only — L1 may be stale).
#pragma unroll
        for (int t = 0; t < 2; t++) {
            const int f = tid + BLK * t;
            const float4 v = __ldcg(&xv[f]);
            unsigned q0 = __float2uint_rn(v.x * qs);
            unsigned q1 = __float2uint_rn(v.y * qs);
            unsigned q2 = __float2uint_rn(v.z * qs);
            unsigned q3 = __float2uint_rn(v.w * qs);
            sxq[f] = q0 | (q1 << 8) | (q2 << 16) | (q3 << 24);
        }
        __syncthreads();

        unsigned a0 = 0, a1 = 0;
#pragma unroll
        for (int it = 0; it < 12; it++) {
            const int c = it * 32 + lane;     // 16-column chunk id
            uint4 xq = sq4[c];
            uint4 m0 = __ldg(&M4[rb + c]);                 // L1-cached
            uint4 m1 = __ldg(&M4[rb + (NPTS / 16) + c]);
            a0 = __dp4a(m0.x, xq.x, a0);
            a0 = __dp4a(m0.y, xq.y, a0);
            a0 = __dp4a(m0.z, xq.z, a0);
            a0 = __dp4a(m0.w, xq.w, a0);
            a1 = __dp4a(m1.x, xq.x, a1);
            a1 = __dp4a(m1.y, xq.y, a1);
            a1 = __dp4a(m1.z, xq.z, a1);
            a1 = __dp4a(m1.w, xq.w, a1);
        }
#pragma unroll
        for (int o = 16; o; o >>= 1) {
            a0 += __shfl_xor_sync(0xffffffffu, a0, o);
            a1 += __shfl_xor_sync(0xffffffffu, a1, o);
        }
        // All lanes hold the totals after the butterfly.
        const float y0 = (float)a0 * outsc;
        const float y1 = (float)a1 * outsc;
        if (lane == 0) {
            y[r0    ] = y0;
            y[r0 + 1] = y1;
            swp[warp] = fmaf(y0, y0, y1 * y1);
            swm[warp] = fmaxf(y0, y1);
        }
        __syncthreads();
        if (tid == 0) {
            float ps = 0.0f, pm = 0.0f;
#pragma unroll
            for (int w = 0; w < 24; w++) {
                ps += swp[w];
                pm = fmaxf(pm, swm[w]);
            }
            d_pn[blockIdx.x] = make_float2(ps, pm);
        }
        grid_barrier();   // includes __threadfence (by tid 0, after its write)
    }

    // Final normalization. Last result is in d_v0 (k=9 wrote y=d_v0).
    {
        float ss = 0.0f;
        const float4* xv = reinterpret_cast<const float4*>(d_v0);
#pragma unroll
        for (int t = 0; t < 2; t++) {
            float4 v = __ldcg(&xv[tid + BLK * t]);
            ss = fmaf(v.x, v.x, fmaf(v.y, v.y,
                 fmaf(v.z, v.z, fmaf(v.w, v.w, ss))));
        }
#pragma unroll
        for (int o = 16; o; o >>= 1) ss += __shfl_xor_sync(0xffffffffu, ss, o);
        if (lane == 0) swp[warp] = ss;
        __syncthreads();
        ss = 0.0f;
#pragma unroll
        for (int w = 0; w < 24; w++) ss += swp[w];
        const float inv = 1.0f / (sqrtf(ss) + 1e-6f);
        if (tid < 48) {
            const int i = blockIdx.x * 48 + tid;
            out[i] = __ldcg(&d_v0[i]) * inv;
        }
    }
}

extern "C" void kernel_launch(void* const* d_in, const int* in_sizes, int n_in,
                              void* d_out, int out_size) {
    const float* p2 = (const float*)d_in[0];  // ipts2d (N,2) fp32
    const float* p3 = (const float*)d_in[1];  // ipts3d (N,3) fp32

    dim3 bgrid(48, 48);                       // 128x128 tiles; ti<=tj compute
    k_build<<<bgrid, 256>>>(p2, p3);
    k_iter<<<GRID, BLK>>>((float*)d_out);     // persistent: iters 1-9 + final
}

// round 16
// speedup vs baseline: 1.0560x; 1.0138x over previous
#include <cuda_runtime.h>

#define NPTS 6144
#define NITERS 10
#define GRID 128          // persistent grid: 1 CTA/SM (best measured shape)
#define BLK 768           // 24 warps x 2 rows = 48 rows/CTA
#define NTILES 1176       // 48*49/2 upper-triangle 128x128 tiles

// Scratch (static device globals — allocation-free per harness rules)
__device__ unsigned char d_M[(size_t)NPTS * NPTS];   // 37.7 MB u8 matrix
__device__ unsigned d_part[48][NPTS];                // per-column-tile rowsums
__device__ float d_v0[NPTS];
__device__ float d_v1[NPTS];
__device__ unsigned g_cnt;   // monotone grid-barrier ticket (survives replays)

__device__ __forceinline__ float fsqrt_approx(float x) {
    float r;
    asm("sqrt.approx.f32 %0, %1;" : "=f"(r) : "f"(x));
    return r;
}

// ---- packed f32x2 helpers (sm_103a) ----
typedef unsigned long long u64t;
__device__ __forceinline__ u64t pk2(float lo, float hi) {
    u64t r; asm("mov.b64 %0, {%1, %2};" : "=l"(r) : "f"(lo), "f"(hi)); return r;
}
__device__ __forceinline__ void upk2(float& lo, float& hi, u64t v) {
    asm("mov.b64 {%0, %1}, %2;" : "=f"(lo), "=f"(hi) : "l"(v));
}
__device__ __forceinline__ u64t add2(u64t a, u64t b) {
    u64t r; asm("add.rn.f32x2 %0, %1, %2;" : "=l"(r) : "l"(a), "l"(b)); return r;
}
__device__ __forceinline__ u64t mul2(u64t a, u64t b) {
    u64t r; asm("mul.rn.f32x2 %0, %1, %2;" : "=l"(r) : "l"(a), "l"(b)); return r;
}
__device__ __forceinline__ u64t fma2(u64t a, u64t b, u64t c) {
    u64t r; asm("fma.rn.f32x2 %0, %1, %2, %3;" : "=l"(r) : "l"(a), "l"(b), "l"(c));
    return r;
}

// Build M in u8 fixed-point, SYMMETRIC (R11 version — fastest measured).
// Grid is now LINEAR over the 1176 upper-triangle tiles (no dead blocks);
// (ti,tj) decoded from blockIdx.x by closed-form triangular decode with
// integer guard loops (exact). Everything else identical to R11:
// mirror tile via in-register 8x8 byte transpose, direct stores;
// M[i][j] == M[j][i] bit-exactly; iteration-0 rowsums into d_part.
__global__ void __launch_bounds__(256) k_build(const float* __restrict__ p2,
                                               const float* __restrict__ p3) {
    // Triangular decode: offset(t) = t*(97-t)/2; largest ti with off<=b.
    const int b = blockIdx.x;
    int ti = (int)((97.0 - sqrt(97.0 * 97.0 - 8.0 * (double)b)) * 0.5);
    if (ti < 0) ti = 0;
    if (ti > 47) ti = 47;
    while (ti > 0 && (ti * (97 - ti)) / 2 > b) ti--;
    while (ti < 47 && ((ti + 1) * (96 - ti)) / 2 <= b) ti++;
    const int tj = ti + (b - (ti * (97 - ti)) / 2);

    const int tid = threadIdx.x;
    const int tx = tid & 15;          // col group within tile
    const int ty = tid >> 4;          // row group within tile
    const int C0 = tj * 128;
    const int R0 = ti * 128;
    const int j0 = C0 + tx * 8;       // 8 cols
    const int rr0 = R0 + ty * 8;      // 8 rows

    const float4* p2v = reinterpret_cast<const float4*>(p2);
    const float4* p3v = reinterpret_cast<const float4*>(p3);

    u64t ncx[4], ncy[4], n3x[4], n3y[4], n3z[4];
#pragma unroll
    for (int k = 0; k < 4; k++) {
        float4 a = __ldg(&p2v[j0 / 2 + k]);
        ncx[k] = pk2(-a.x, -a.z);
        ncy[k] = pk2(-a.y, -a.w);
    }
    {
        float q3[24];
#pragma unroll
        for (int k = 0; k < 6; k++) {
            float4 a = __ldg(&p3v[(3 * j0) / 4 + k]);
            q3[4*k] = a.x; q3[4*k+1] = a.y; q3[4*k+2] = a.z; q3[4*k+3] = a.w;
        }
#pragma unroll
        for (int k = 0; k < 4; k++) {
            n3x[k] = pk2(-q3[6*k],   -q3[6*k+3]);
            n3y[k] = pk2(-q3[6*k+1], -q3[6*k+4]);
            n3z[k] = pk2(-q3[6*k+2], -q3[6*k+5]);
        }
    }
    float rx[8], ry[8];
#pragma unroll
    for (int k = 0; k < 4; k++) {
        float4 a = __ldg(&p2v[rr0 / 2 + k]);
        rx[2*k] = a.x; ry[2*k] = a.y; rx[2*k+1] = a.z; ry[2*k+1] = a.w;
    }
    float r3[24];
#pragma unroll
    for (int k = 0; k < 6; k++) {
        float4 a = __ldg(&p3v[(3 * rr0) / 4 + k]);
        r3[4*k] = a.x; r3[4*k+1] = a.y; r3[4*k+2] = a.z; r3[4*k+3] = a.w;
    }

    const u64t NEG2  = pk2(-2.0f, -2.0f);
    const u64t NEGK  = pk2(-25500.0f, -25500.0f);
    const u64t MAGIC = pk2(8388863.0f, 8388863.0f);

    unsigned tl[8], th[8], rs[8];
#pragma unroll
    for (int r = 0; r < 8; r++) {
        const u64t sx2 = pk2(rx[r], rx[r]);
        const u64t sy2 = pk2(ry[r], ry[r]);
        const u64t sx3 = pk2(r3[3*r],   r3[3*r]);
        const u64t sy3 = pk2(r3[3*r+1], r3[3*r+1]);
        const u64t sz3 = pk2(r3[3*r+2], r3[3*r+2]);
        unsigned u[8];
#pragma unroll
        for (int p = 0; p < 4; p++) {
            u64t dx = add2(sx2, ncx[p]);
            u64t dy = add2(sy2, ncy[p]);
            u64t a  = fma2(dx, dx, mul2(dy, dy));
            u64t d0 = add2(sx3, n3x[p]);
            u64t d1 = add2(sy3, n3y[p]);
            u64t d2 = add2(sz3, n3z[p]);
            u64t bb = fma2(d2, d2, fma2(d1, d1, mul2(d0, d0)));
            u64t ab = mul2(a, bb);
            u64t apb = add2(a, bb);
            float ab0, ab1;
            upk2(ab0, ab1, ab);
            u64t s  = pk2(fsqrt_approx(ab0), fsqrt_approx(ab1));
            u64t cr = fma2(NEG2, s, apb);       // (sqrt a - sqrt b)^2
            u64t t  = fma2(NEGK, cr, MAGIC);    // 2^23 + 255 - 25500*cr
            float t0, t1;
            upk2(t0, t1, t);
            t0 = fminf(fmaxf(t0, 8388608.0f), 8388863.0f);
            t1 = fminf(fmaxf(t1, 8388608.0f), 8388863.0f);
            u[2*p]   = __float_as_uint(t0);     // byte = low 8 mantissa bits
            u[2*p+1] = __float_as_uint(t1);
        }
        unsigned w0 = __byte_perm(__byte_perm(u[0], u[1], 0x0040),
                                  __byte_perm(u[2], u[3], 0x0040), 0x5410);
        unsigned w1 = __byte_perm(__byte_perm(u[4], u[5], 0x0040),
                                  __byte_perm(u[6], u[7], 0x0040), 0x5410);
        *reinterpret_cast<uint2*>(&d_M[(size_t)(rr0 + r) * NPTS + j0]) =
            make_uint2(w0, w1);
        tl[r] = w0; th[r] = w1;
        rs[r] = __dp4a(w0, 0x01010101u, __dp4a(w1, 0x01010101u, 0u));
    }

    // Row partials: reduce rs[] across tx (16 lanes of a half-warp).
#pragma unroll
    for (int r = 0; r < 8; r++) {
        unsigned v = rs[r];
        v += __shfl_xor_sync(0xffffffffu, v, 1);
        v += __shfl_xor_sync(0xffffffffu, v, 2);
        v += __shfl_xor_sync(0xffffffffu, v, 4);
        v += __shfl_xor_sync(0xffffffffu, v, 8);
        if (tx == 0) d_part[tj][rr0 + r] = v;
    }

    __shared__ unsigned scol[128][17];   // padded col-partial staging

    if (ti != tj) {
        // 8x8 byte transpose in registers (PRMT).
        unsigned ol[8], oh[8];
#pragma unroll
        for (int half = 0; half < 2; half++) {          // out cols 0-3 / 4-7
            const unsigned* in = half ? th : tl;
            unsigned* o03 = half ? (ol + 4) : ol;
            unsigned* o47 = half ? (oh + 4) : oh;
            unsigned p0 = __byte_perm(in[0], in[1], 0x5140);
            unsigned p1 = __byte_perm(in[0], in[1], 0x7362);
            unsigned q0 = __byte_perm(in[2], in[3], 0x5140);
            unsigned q1 = __byte_perm(in[2], in[3], 0x7362);
            o03[0] = __byte_perm(p0, q0, 0x5410);
            o03[1] = __byte_perm(p0, q0, 0x7632);
            o03[2] = __byte_perm(p1, q1, 0x5410);
            o03[3] = __byte_perm(p1, q1, 0x7632);
            unsigned s0 = __byte_perm(in[4], in[5], 0x5140);
            unsigned s1 = __byte_perm(in[4], in[5], 0x7362);
            unsigned t0 = __byte_perm(in[6], in[7], 0x5140);
            unsigned t1 = __byte_perm(in[6], in[7], 0x7362);
            o47[0] = __byte_perm(s0, t0, 0x5410);
            o47[1] = __byte_perm(s0, t0, 0x7632);
            o47[2] = __byte_perm(s1, t1, 0x5410);
            o47[3] = __byte_perm(s1, t1, 0x7632);
        }
        // Store mirror tile + per-thread column sums.
#pragma unroll
        for (int c = 0; c < 8; c++) {
            *reinterpret_cast<uint2*>(
                &d_M[(size_t)(j0 + c) * NPTS + rr0]) = make_uint2(ol[c], oh[c]);
            scol[tx * 8 + c][ty] =
                __dp4a(ol[c], 0x01010101u, __dp4a(oh[c], 0x01010101u, 0u));
        }
        __syncthreads();
        if (tid < 128) {
            unsigned s = 0;
#pragma unroll
            for (int t = 0; t < 16; t++) s += scol[tid][t];
            d_part[ti][C0 + tid] = s;   // col partials = mirror-tile rows
        }
    }
}

// Software grid barrier. Monotone ticket counter: works across graph replays
// without reset (counter is always a multiple of GRID at barrier boundaries).
__device__ __forceinline__ void grid_barrier() {
    __syncthreads();
    if (threadIdx.x == 0) {
        __threadfence();
        unsigned old = atomicAdd(&g_cnt, 1u);
        unsigned target = old - (old % GRID) + GRID;
        while (*((volatile unsigned*)&g_cnt) < target) __nanosleep(32);
    }
    __syncthreads();
}

// Persistent kernel (R11, unchanged — best measured): iterations 1..9 +
// final normalization. Iteration 0 (x = ones) lives in d_part as 48 exact
// integer partials per row; prologue reduces this CTA's 48 rows into
// d_v1 = rowsum/255 (exact: sums < 2^24), then one grid barrier publishes
// the full vector. x quantized to a single u8 plane scaled by its max;
// exact u32 dp4a accumulation; norm from unquantized floats.
// grid=128, block=768: 24 warps x 2 rows = 48 rows/CTA, one CTA per SM so
// M rows stay hot in L1 (__ldg); x/y vectors bypass stale L1 (__ldcg).
__global__ void __launch_bounds__(BLK) k_iter(float* __restrict__ out) {
    __shared__ unsigned sxq[NPTS / 4];    // u8 plane of xq
    __shared__ float red[24];
    __shared__ float redm[24];

    const int tid = threadIdx.x;
    const int warp = tid >> 5, lane = tid & 31;
    const int r0 = blockIdx.x * 48 + warp * 2;
    const uint4* M4  = reinterpret_cast<const uint4*>(d_M);
    const uint4* sq4 = reinterpret_cast<const uint4*>(sxq);
    const size_t rb = (size_t)r0 * (NPTS / 16);

    // Prologue: v1[row] = (sum of 48 column-tile partials)/255 for this
    // CTA's 48 rows. 12 FULL warps (tid < 384); shuffles are full-warp safe.
    if (tid < 384) {
        const int rloc = tid >> 3;
        const int seg  = tid & 7;
        const int row  = blockIdx.x * 48 + rloc;
        unsigned s = 0;
#pragma unroll
        for (int a = 0; a < 6; a++)
            s += d_part[seg * 6 + a][row];
        s += __shfl_xor_sync(0xffffffffu, s, 1);
        s += __shfl_xor_sync(0xffffffffu, s, 2);
        s += __shfl_xor_sync(0xffffffffu, s, 4);
        if (seg == 0) d_v1[row] = (float)s * (1.0f / 255.0f);
    }
    grid_barrier();

    for (int k = 1; k < NITERS; k++) {
        float* __restrict__ y = (k & 1) ? d_v0 : d_v1;
        const float4* xv = reinterpret_cast<const float4*>(
            (k & 1) ? d_v1 : d_v0);

        // Stage x (L2 only — L1 may hold stale lines), norm + max.
        float4 v[2];
        float ss = 0.0f, mx = 0.0f;
#pragma unroll
        for (int t = 0; t < 2; t++) {
            v[t] = __ldcg(&xv[tid + BLK * t]);
            ss = fmaf(v[t].x, v[t].x, fmaf(v[t].y, v[t].y,
                 fmaf(v[t].z, v[t].z, fmaf(v[t].w, v[t].w, ss))));
            mx = fmaxf(mx, fmaxf(fmaxf(v[t].x, v[t].y),
                                 fmaxf(v[t].z, v[t].w)));
        }
#pragma unroll
        for (int o = 16; o; o >>= 1) {
            ss += __shfl_xor_sync(0xffffffffu, ss, o);
            mx = fmaxf(mx, __shfl_xor_sync(0xffffffffu, mx, o));
        }
        if (lane == 0) { red[warp] = ss; redm[warp] = mx; }
        __syncthreads();
        ss = 0.0f; mx = 0.0f;
#pragma unroll
        for (int w = 0; w < 24; w++) {
            ss += red[w];
            mx = fmaxf(mx, redm[w]);
        }

        const float inv = 1.0f / (sqrtf(ss) + 1e-6f);
        const float qs  = 255.0f / mx;                 // max-scaled u8 quant
        const float outsc = mx * inv * (1.0f / 65025.0f);

#pragma unroll
        for (int t = 0; t < 2; t++) {
            unsigned q0 = __float2uint_rn(v[t].x * qs);
            unsigned q1 = __float2uint_rn(v[t].y * qs);
            unsigned q2 = __float2uint_rn(v[t].z * qs);
            unsigned q3 = __float2uint_rn(v[t].w * qs);
            sxq[tid + BLK * t] = q0 | (q1 << 8) | (q2 << 16) | (q3 << 24);
        }
        __syncthreads();

        unsigned a0 = 0, a1 = 0;
#pragma unroll
        for (int it = 0; it < 12; it++) {
            const int c = it * 32 + lane;     // 16-column chunk id
            uint4 xq = sq4[c];
            uint4 m0 = __ldg(&M4[rb + c]);                 // L1-cached
            uint4 m1 = __ldg(&M4[rb + (NPTS / 16) + c]);
            a0 = __dp4a(m0.x, xq.x, a0);
            a0 = __dp4a(m0.y, xq.y, a0);
            a0 = __dp4a(m0.z, xq.z, a0);
            a0 = __dp4a(m0.w, xq.w, a0);
            a1 = __dp4a(m1.x, xq.x, a1);
            a1 = __dp4a(m1.y, xq.y, a1);
            a1 = __dp4a(m1.z, xq.z, a1);
            a1 = __dp4a(m1.w, xq.w, a1);
        }
#pragma unroll
        for (int o = 16; o; o >>= 1) {
            a0 += __shfl_xor_sync(0xffffffffu, a0, o);
            a1 += __shfl_xor_sync(0xffffffffu, a1, o);
        }
        if (lane == 0) {
            y[r0    ] = (float)a0 * outsc;
            y[r0 + 1] = (float)a1 * outsc;
        }
        grid_barrier();   // includes __threadfence before arrival
    }

    // Final normalization. Last result is in d_v0 (k=9 wrote y=d_v0).
    {
        float ss = 0.0f;
        const float4* xv = reinterpret_cast<const float4*>(d_v0);
#pragma unroll
        for (int t = 0; t < 2; t++) {
            float4 v = __ldcg(&xv[tid + BLK * t]);
            ss = fmaf(v.x, v.x, fmaf(v.y, v.y,
                 fmaf(v.z, v.z, fmaf(v.w, v.w, ss))));
        }
#pragma unroll
        for (int o = 16; o; o >>= 1) ss += __shfl_xor_sync(0xffffffffu, ss, o);
        if (lane == 0) red[warp] = ss;
        __syncthreads();
        ss = 0.0f;
#pragma unroll
        for (int w = 0; w < 24; w++) ss += red[w];
        const float inv = 1.0f / (sqrtf(ss) + 1e-6f);
        if (tid < 48) {
            const int i = blockIdx.x * 48 + tid;
            out[i] = __ldcg(&d_v0[i]) * inv;
        }
    }
}

extern "C" void kernel_launch(void* const* d_in, const int* in_sizes, int n_in,
                              void* d_out, int out_size) {
    const float* p2 = (const float*)d_in[0];  // ipts2d (N,2) fp32
    const float* p3 = (const float*)d_in[1];  // ipts3d (N,3) fp32

    k_build<<<NTILES, 256>>>(p2, p3);         // linear triangle grid, no dead blocks
    k_iter<<<GRID, BLK>>>((float*)d_out);     // persistent: iters 1-9 + final
}

// round 17
// speedup vs baseline: 1.0888x; 1.0310x over previous
#include <cuda_runtime.h>

#define NPTS 6144
#define NITERS 10
#define GRID 128          // persistent grid: 1 CTA/SM (best measured shape)
#define BLK 768           // 24 warps x 2 rows = 48 rows/CTA

// Scratch (static device globals — allocation-free per harness rules)
__device__ unsigned char d_M[(size_t)NPTS * NPTS];   // 37.7 MB u8 matrix
__device__ unsigned d_part[48][NPTS];                // per-column-tile rowsums
__device__ float d_v0[NPTS];
__device__ float d_v1[NPTS];
__device__ unsigned g_cnt;   // monotone grid-barrier ticket (survives replays)

__device__ __forceinline__ float fsqrt_approx(float x) {
    float r;
    asm("sqrt.approx.f32 %0, %1;" : "=f"(r) : "f"(x));
    return r;
}

// ---- packed f32x2 helpers (sm_103a) ----
typedef unsigned long long u64t;
__device__ __forceinline__ u64t pk2(float lo, float hi) {
    u64t r; asm("mov.b64 %0, {%1, %2};" : "=l"(r) : "f"(lo), "f"(hi)); return r;
}
__device__ __forceinline__ void upk2(float& lo, float& hi, u64t v) {
    asm("mov.b64 {%0, %1}, %2;" : "=f"(lo), "=f"(hi) : "l"(v));
}
__device__ __forceinline__ u64t add2(u64t a, u64t b) {
    u64t r; asm("add.rn.f32x2 %0, %1, %2;" : "=l"(r) : "l"(a), "l"(b)); return r;
}
__device__ __forceinline__ u64t mul2(u64t a, u64t b) {
    u64t r; asm("mul.rn.f32x2 %0, %1, %2;" : "=l"(r) : "l"(a), "l"(b)); return r;
}
__device__ __forceinline__ u64t fma2(u64t a, u64t b, u64t c) {
    u64t r; asm("fma.rn.f32x2 %0, %1, %2, %3;" : "=l"(r) : "l"(a), "l"(b), "l"(c));
    return r;
}

// Build M in u8 fixed-point, SYMMETRIC (R11 version — fastest measured).
// Only tiles with tj >= ti computed (128x128 per block, 8x8 per thread);
// the mirror tile is produced by an in-register 8x8 byte transpose (PRMT)
// and stored directly. M[i][j] == M[j][i] bit-exactly (negated diffs
// square identically). Rowsums for iteration 0 (x = ones) go to
// d_part[48][NPTS]: row-partials via warp shuffles, col-partials via smem
// reduction of the mirror tile. Every slot written exactly once.
__global__ void __launch_bounds__(256) k_build(const float* __restrict__ p2,
                                               const float* __restrict__ p3) {
    const int ti = blockIdx.y;        // row tile
    const int tj = blockIdx.x;        // col tile
    if (ti > tj) return;              // symmetric: upper triangle only

    const int tid = threadIdx.x;
    const int tx = tid & 15;          // col group within tile
    const int ty = tid >> 4;          // row group within tile
    const int C0 = tj * 128;
    const int R0 = ti * 128;
    const int j0 = C0 + tx * 8;       // 8 cols
    const int rr0 = R0 + ty * 8;      // 8 rows

    const float4* p2v = reinterpret_cast<const float4*>(p2);
    const float4* p3v = reinterpret_cast<const float4*>(p3);

    u64t ncx[4], ncy[4], n3x[4], n3y[4], n3z[4];
#pragma unroll
    for (int k = 0; k < 4; k++) {
        float4 a = __ldg(&p2v[j0 / 2 + k]);
        ncx[k] = pk2(-a.x, -a.z);
        ncy[k] = pk2(-a.y, -a.w);
    }
    {
        float q3[24];
#pragma unroll
        for (int k = 0; k < 6; k++) {
            float4 a = __ldg(&p3v[(3 * j0) / 4 + k]);
            q3[4*k] = a.x; q3[4*k+1] = a.y; q3[4*k+2] = a.z; q3[4*k+3] = a.w;
        }
#pragma unroll
        for (int k = 0; k < 4; k++) {
            n3x[k] = pk2(-q3[6*k],   -q3[6*k+3]);
            n3y[k] = pk2(-q3[6*k+1], -q3[6*k+4]);
            n3z[k] = pk2(-q3[6*k+2], -q3[6*k+5]);
        }
    }
    float rx[8], ry[8];
#pragma unroll
    for (int k = 0; k < 4; k++) {
        float4 a = __ldg(&p2v[rr0 / 2 + k]);
        rx[2*k] = a.x; ry[2*k] = a.y; rx[2*k+1] = a.z; ry[2*k+1] = a.w;
    }
    float r3[24];
#pragma unroll
    for (int k = 0; k < 6; k++) {
        float4 a = __ldg(&p3v[(3 * rr0) / 4 + k]);
        r3[4*k] = a.x; r3[4*k+1] = a.y; r3[4*k+2] = a.z; r3[4*k+3] = a.w;
    }

    const u64t NEG2  = pk2(-2.0f, -2.0f);
    const u64t NEGK  = pk2(-25500.0f, -25500.0f);
    const u64t MAGIC = pk2(8388863.0f, 8388863.0f);

    unsigned tl[8], th[8], rs[8];
#pragma unroll
    for (int r = 0; r < 8; r++) {
        const u64t sx2 = pk2(rx[r], rx[r]);
        const u64t sy2 = pk2(ry[r], ry[r]);
        const u64t sx3 = pk2(r3[3*r],   r3[3*r]);
        const u64t sy3 = pk2(r3[3*r+1], r3[3*r+1]);
        const u64t sz3 = pk2(r3[3*r+2], r3[3*r+2]);
        unsigned u[8];
#pragma unroll
        for (int p = 0; p < 4; p++) {
            u64t dx = add2(sx2, ncx[p]);
            u64t dy = add2(sy2, ncy[p]);
            u64t a  = fma2(dx, dx, mul2(dy, dy));
            u64t d0 = add2(sx3, n3x[p]);
            u64t d1 = add2(sy3, n3y[p]);
            u64t d2 = add2(sz3, n3z[p]);
            u64t b  = fma2(d2, d2, fma2(d1, d1, mul2(d0, d0)));
            u64t ab = mul2(a, b);
            u64t apb = add2(a, b);
            float ab0, ab1;
            upk2(ab0, ab1, ab);
            u64t s  = pk2(fsqrt_approx(ab0), fsqrt_approx(ab1));
            u64t cr = fma2(NEG2, s, apb);       // (sqrt a - sqrt b)^2
            u64t t  = fma2(NEGK, cr, MAGIC);    // 2^23 + 255 - 25500*cr
            float t0, t1;
            upk2(t0, t1, t);
            t0 = fminf(fmaxf(t0, 8388608.0f), 8388863.0f);
            t1 = fminf(fmaxf(t1, 8388608.0f), 8388863.0f);
            u[2*p]   = __float_as_uint(t0);     // byte = low 8 mantissa bits
            u[2*p+1] = __float_as_uint(t1);
        }
        unsigned w0 = __byte_perm(__byte_perm(u[0], u[1], 0x0040),
                                  __byte_perm(u[2], u[3], 0x0040), 0x5410);
        unsigned w1 = __byte_perm(__byte_perm(u[4], u[5], 0x0040),
                                  __byte_perm(u[6], u[7], 0x0040), 0x5410);
        *reinterpret_cast<uint2*>(&d_M[(size_t)(rr0 + r) * NPTS + j0]) =
            make_uint2(w0, w1);
        tl[r] = w0; th[r] = w1;
        rs[r] = __dp4a(w0, 0x01010101u, __dp4a(w1, 0x01010101u, 0u));
    }

    // Row partials: reduce rs[] across tx (16 lanes of a half-warp).
#pragma unroll
    for (int r = 0; r < 8; r++) {
        unsigned v = rs[r];
        v += __shfl_xor_sync(0xffffffffu, v, 1);
        v += __shfl_xor_sync(0xffffffffu, v, 2);
        v += __shfl_xor_sync(0xffffffffu, v, 4);
        v += __shfl_xor_sync(0xffffffffu, v, 8);
        if (tx == 0) d_part[tj][rr0 + r] = v;
    }

    __shared__ unsigned scol[128][17];   // padded col-partial staging

    if (ti != tj) {
        // 8x8 byte transpose in registers (PRMT).
        unsigned ol[8], oh[8];
#pragma unroll
        for (int half = 0; half < 2; half++) {          // out cols 0-3 / 4-7
            const unsigned* in = half ? th : tl;
            unsigned* o03 = half ? (ol + 4) : ol;
            unsigned* o47 = half ? (oh + 4) : oh;
            unsigned p0 = __byte_perm(in[0], in[1], 0x5140);
            unsigned p1 = __byte_perm(in[0], in[1], 0x7362);
            unsigned q0 = __byte_perm(in[2], in[3], 0x5140);
            unsigned q1 = __byte_perm(in[2], in[3], 0x7362);
            o03[0] = __byte_perm(p0, q0, 0x5410);
            o03[1] = __byte_perm(p0, q0, 0x7632);
            o03[2] = __byte_perm(p1, q1, 0x5410);
            o03[3] = __byte_perm(p1, q1, 0x7632);
            unsigned s0 = __byte_perm(in[4], in[5], 0x5140);
            unsigned s1 = __byte_perm(in[4], in[5], 0x7362);
            unsigned t0 = __byte_perm(in[6], in[7], 0x5140);
            unsigned t1 = __byte_perm(in[6], in[7], 0x7362);
            o47[0] = __byte_perm(s0, t0, 0x5410);
            o47[1] = __byte_perm(s0, t0, 0x7632);
            o47[2] = __byte_perm(s1, t1, 0x5410);
            o47[3] = __byte_perm(s1, t1, 0x7632);
        }
        // Store mirror tile + per-thread column sums.
#pragma unroll
        for (int c = 0; c < 8; c++) {
            *reinterpret_cast<uint2*>(
                &d_M[(size_t)(j0 + c) * NPTS + rr0]) = make_uint2(ol[c], oh[c]);
            scol[tx * 8 + c][ty] =
                __dp4a(ol[c], 0x01010101u, __dp4a(oh[c], 0x01010101u, 0u));
        }
        __syncthreads();
        if (tid < 128) {
            unsigned s = 0;
#pragma unroll
            for (int t = 0; t < 16; t++) s += scol[tid][t];
            d_part[ti][C0 + tid] = s;   // col partials = mirror-tile rows
        }
    }
}

// Software grid barrier. Monotone ticket counter: works across graph replays
// without reset (counter is always a multiple of GRID at barrier boundaries).
__device__ __forceinline__ void grid_barrier() {
    __syncthreads();
    if (threadIdx.x == 0) {
        __threadfence();
        unsigned old = atomicAdd(&g_cnt, 1u);
        unsigned target = old - (old % GRID) + GRID;
        while (*((volatile unsigned*)&g_cnt) < target) __nanosleep(32);
    }
    __syncthreads();
}

// Persistent kernel (R11 champion, one micro-reorder: M LDGs issued before
// the xq LDS in the mainloop so global latency overlaps the shared load).
// Iterations 1..9 + final normalization. Iteration 0 (x = ones) lives in
// d_part as 48 exact integer partials per row; prologue reduces this CTA's
// 48 rows into d_v1 = rowsum/255 (exact: sums < 2^24), one grid barrier
// publishes the vector. x quantized to a single u8 plane scaled by its
// max; exact u32 dp4a accumulation; norm from unquantized floats.
// grid=128, block=768: 24 warps x 2 rows = 48 rows/CTA, one CTA per SM so
// M rows stay hot in L1 (__ldg); x/y vectors bypass stale L1 (__ldcg).
__global__ void __launch_bounds__(BLK) k_iter(float* __restrict__ out) {
    __shared__ unsigned sxq[NPTS / 4];    // u8 plane of xq
    __shared__ float red[24];
    __shared__ float redm[24];

    const int tid = threadIdx.x;
    const int warp = tid >> 5, lane = tid & 31;
    const int r0 = blockIdx.x * 48 + warp * 2;
    const uint4* M4  = reinterpret_cast<const uint4*>(d_M);
    const uint4* sq4 = reinterpret_cast<const uint4*>(sxq);
    const size_t rb = (size_t)r0 * (NPTS / 16);

    // Prologue: v1[row] = (sum of 48 column-tile partials)/255 for this
    // CTA's 48 rows. 12 FULL warps (tid < 384); shuffles full-warp safe.
    if (tid < 384) {
        const int rloc = tid >> 3;
        const int seg  = tid & 7;
        const int row  = blockIdx.x * 48 + rloc;
        unsigned s = 0;
#pragma unroll
        for (int a = 0; a < 6; a++)
            s += d_part[seg * 6 + a][row];
        s += __shfl_xor_sync(0xffffffffu, s, 1);
        s += __shfl_xor_sync(0xffffffffu, s, 2);
        s += __shfl_xor_sync(0xffffffffu, s, 4);
        if (seg == 0) d_v1[row] = (float)s * (1.0f / 255.0f);
    }
    grid_barrier();

    for (int k = 1; k < NITERS; k++) {
        float* __restrict__ y = (k & 1) ? d_v0 : d_v1;
        const float4* xv = reinterpret_cast<const float4*>(
            (k & 1) ? d_v1 : d_v0);

        // Stage x (L2 only — L1 may hold stale lines), norm + max.
        // This redundant reduction is effectively free: it rides along the
        // x loads every CTA needs anyway (R15 showed centralizing it loses).
        float4 v[2];
        float ss = 0.0f, mx = 0.0f;
#pragma unroll
        for (int t = 0; t < 2; t++) {
            v[t] = __ldcg(&xv[tid + BLK * t]);
            ss = fmaf(v[t].x, v[t].x, fmaf(v[t].y, v[t].y,
                 fmaf(v[t].z, v[t].z, fmaf(v[t].w, v[t].w, ss))));
            mx = fmaxf(mx, fmaxf(fmaxf(v[t].x, v[t].y),
                                 fmaxf(v[t].z, v[t].w)));
        }
#pragma unroll
        for (int o = 16; o; o >>= 1) {
            ss += __shfl_xor_sync(0xffffffffu, ss, o);
            mx = fmaxf(mx, __shfl_xor_sync(0xffffffffu, mx, o));
        }
        if (lane == 0) { red[warp] = ss; redm[warp] = mx; }
        __syncthreads();
        ss = 0.0f; mx = 0.0f;
#pragma unroll
        for (int w = 0; w < 24; w++) {
            ss += red[w];
            mx = fmaxf(mx, redm[w]);
        }

        const float inv = 1.0f / (sqrtf(ss) + 1e-6f);
        const float qs  = 255.0f / mx;                 // max-scaled u8 quant
        const float outsc = mx * inv * (1.0f / 65025.0f);

#pragma unroll
        for (int t = 0; t < 2; t++) {
            unsigned q0 = __float2uint_rn(v[t].x * qs);
            unsigned q1 = __float2uint_rn(v[t].y * qs);
            unsigned q2 = __float2uint_rn(v[t].z * qs);
            unsigned q3 = __float2uint_rn(v[t].w * qs);
            sxq[tid + BLK * t] = q0 | (q1 << 8) | (q2 << 16) | (q3 << 24);
        }
        __syncthreads();

        unsigned a0 = 0, a1 = 0;
#pragma unroll
        for (int it = 0; it < 12; it++) {
            const int c = it * 32 + lane;     // 16-column chunk id
            uint4 m0 = __ldg(&M4[rb + c]);                 // L1-cached; issue
            uint4 m1 = __ldg(&M4[rb + (NPTS / 16) + c]);   // globals first
            uint4 xq = sq4[c];
            a0 = __dp4a(m0.x, xq.x, a0);
            a0 = __dp4a(m0.y, xq.y, a0);
            a0 = __dp4a(m0.z, xq.z, a0);
            a0 = __dp4a(m0.w, xq.w, a0);
            a1 = __dp4a(m1.x, xq.x, a1);
            a1 = __dp4a(m1.y, xq.y, a1);
            a1 = __dp4a(m1.z, xq.z, a1);
            a1 = __dp4a(m1.w, xq.w, a1);
        }
#pragma unroll
        for (int o = 16; o; o >>= 1) {
            a0 += __shfl_xor_sync(0xffffffffu, a0, o);
            a1 += __shfl_xor_sync(0xffffffffu, a1, o);
        }
        if (lane == 0) {
            y[r0    ] = (float)a0 * outsc;
            y[r0 + 1] = (float)a1 * outsc;
        }
        grid_barrier();   // includes __threadfence before arrival
    }

    // Final normalization. Last result is in d_v0 (k=9 wrote y=d_v0).
    {
        float ss = 0.0f;
        const float4* xv = reinterpret_cast<const float4*>(d_v0);
#pragma unroll
        for (int t = 0; t < 2; t++) {
            float4 v = __ldcg(&xv[tid + BLK * t]);
            ss = fmaf(v.x, v.x, fmaf(v.y, v.y,
                 fmaf(v.z, v.z, fmaf(v.w, v.w, ss))));
        }
#pragma unroll
        for (int o = 16; o; o >>= 1) ss += __shfl_xor_sync(0xffffffffu, ss, o);
        if (lane == 0) red[warp] = ss;
        __syncthreads();
        ss = 0.0f;
#pragma unroll
        for (int w = 0; w < 24; w++) ss += red[w];
        const float inv = 1.0f / (sqrtf(ss) + 1e-6f);
        if (tid < 48) {
            const int i = blockIdx.x * 48 + tid;
            out[i] = __ldcg(&d_v0[i]) * inv;
        }
    }
}

extern "C" void kernel_launch(void* const* d_in, const int* in_sizes, int n_in,
                              void* d_out, int out_size) {
    const float* p2 = (const float*)d_in[0];  // ipts2d (N,2) fp32
    const float* p3 = (const float*)d_in[1];  // ipts3d (N,3) fp32

    dim3 bgrid(48, 48);                       // 128x128 tiles; ti<=tj compute
    k_build<<<bgrid, 256>>>(p2, p3);
    k_iter<<<GRID, BLK>>>((float*)d_out);     // persistent: iters 1-9 + final
}